// round 1
// baseline (speedup 1.0000x reference)
#include <cuda_runtime.h>
#include <cstdint>

// Problem constants (fixed by the reference)
#define Bb 2
#define Tt 2048
#define Cc 1024
#define Hh 16
#define Dd 64
#define Pp 2048
#define C3 3072

// Scratch (device globals — no runtime allocation allowed)
__device__ float g_qkv[(size_t)Bb * Tt * C3];   // [B*T, 3C]
__device__ float g_y[(size_t)Bb * Tt * Cc];     // [B*T, C] attention output

// ---------------------------------------------------------------------------
// Tiled FP32 GEMM: C = A[M,K] @ B[K,N], row-major, all dims multiples of 128/16
// BM=BN=128, BK=16, 256 threads, 8x8 per thread.
// ---------------------------------------------------------------------------
__global__ __launch_bounds__(256, 2)
void sgemm_kernel(const float* __restrict__ A, const float* __restrict__ Bm,
                  float* __restrict__ Cm, int M, int N, int K)
{
    __shared__ float As[16][132];   // A tile transposed: As[k][m], padded pitch
    __shared__ float Bs[16][128];   // B tile natural:     Bs[k][n]

    const int tid = threadIdx.x;
    const int tx = tid & 15, ty = tid >> 4;
    const int bm = blockIdx.y * 128, bn = blockIdx.x * 128;

    const int a_row = tid >> 2;          // 0..63
    const int a_col = (tid & 3) << 2;    // 0,4,8,12
    const int b_row = tid >> 5;          // 0..7
    const int b_col = (tid & 31) << 2;   // 0..124

    float acc[8][8];
    #pragma unroll
    for (int i = 0; i < 8; i++)
        #pragma unroll
        for (int j = 0; j < 8; j++) acc[i][j] = 0.f;

    for (int k0 = 0; k0 < K; k0 += 16) {
        #pragma unroll
        for (int r = 0; r < 2; r++) {
            float4 av = *(const float4*)&A[(size_t)(bm + a_row + r*64)*K + k0 + a_col];
            As[a_col+0][a_row + r*64] = av.x;
            As[a_col+1][a_row + r*64] = av.y;
            As[a_col+2][a_row + r*64] = av.z;
            As[a_col+3][a_row + r*64] = av.w;
        }
        #pragma unroll
        for (int r = 0; r < 2; r++) {
            *(float4*)&Bs[b_row + r*8][b_col] =
                *(const float4*)&Bm[(size_t)(k0 + b_row + r*8)*N + bn + b_col];
        }
        __syncthreads();

        #pragma unroll
        for (int k = 0; k < 16; k++) {
            float a[8], bv[8];
            *(float4*)&a[0]  = *(const float4*)&As[k][ty*8];
            *(float4*)&a[4]  = *(const float4*)&As[k][ty*8 + 4];
            *(float4*)&bv[0] = *(const float4*)&Bs[k][tx*8];
            *(float4*)&bv[4] = *(const float4*)&Bs[k][tx*8 + 4];
            #pragma unroll
            for (int i = 0; i < 8; i++)
                #pragma unroll
                for (int j = 0; j < 8; j++)
                    acc[i][j] = fmaf(a[i], bv[j], acc[i][j]);
        }
        __syncthreads();
    }

    #pragma unroll
    for (int i = 0; i < 8; i++) {
        float4 v0 = make_float4(acc[i][0], acc[i][1], acc[i][2], acc[i][3]);
        float4 v1 = make_float4(acc[i][4], acc[i][5], acc[i][6], acc[i][7]);
        size_t row = (size_t)(bm + ty*8 + i);
        *(float4*)&Cm[row*N + bn + tx*8]     = v0;
        *(float4*)&Cm[row*N + bn + tx*8 + 4] = v1;
    }
}

// ---------------------------------------------------------------------------
// Flash attention over [prefix cache (P) + causal self (T)] keys.
// One block = one (b, h, 64-query tile). 256 threads = 16x16 grid, 4x4 micro.
// smem: sQt[d][r] (Q transposed, pre-scaled), sKP (K^T tile, reused as P tile),
//       sV[k][d]. Pitch 68 floats (16B-aligned, conflict-free access patterns).
// ---------------------------------------------------------------------------
#define FP 68

__global__ __launch_bounds__(256)
void flash_kernel(const float* __restrict__ qkv,
                  const float* __restrict__ cache_k,
                  const float* __restrict__ cache_v,
                  float* __restrict__ y)
{
    extern __shared__ float sm[];
    float* sQt = sm;               // [64][FP]  sQt[d*FP + r]
    float* sKP = sm + 64*FP;       // [64][FP]  K^T: [d][c]  /  P: [r][c]
    float* sV  = sm + 2*64*FP;     // [64][FP]  sV[k*FP + d]

    const int tid = threadIdx.x;
    const int tx = tid & 15, ty = tid >> 4;
    const int tx4 = tx * 4, ty4 = ty * 4;
    const int qt = blockIdx.x, h = blockIdx.y, b = blockIdx.z;
    const int q0 = qt * 64;

    const int lr = tid >> 2;       // loader row 0..63
    const int lq = tid & 3;        // loader quad 0..3

    // Load Q tile (transposed + pre-scaled by 1/sqrt(D))
    {
        const float* qr = qkv + ((size_t)(b*Tt + q0 + lr))*C3 + h*Dd;
        #pragma unroll
        for (int u = 0; u < 4; u++) {
            int d4 = (lq + 4*u) * 4;
            float4 v = *(const float4*)&qr[d4];
            sQt[(d4+0)*FP + lr] = v.x * 0.125f;
            sQt[(d4+1)*FP + lr] = v.y * 0.125f;
            sQt[(d4+2)*FP + lr] = v.z * 0.125f;
            sQt[(d4+3)*FP + lr] = v.w * 0.125f;
        }
    }

    float O[4][4];
    float m_i[4], l_i[4];
    #pragma unroll
    for (int i = 0; i < 4; i++) {
        m_i[i] = -1e30f; l_i[i] = 0.f;
        #pragma unroll
        for (int j = 0; j < 4; j++) O[i][j] = 0.f;
    }

    const int nPrefix = Pp / 64;          // 32
    const int nBlk = nPrefix + qt + 1;    // prefix + causal self tiles

    for (int jb = 0; jb < nBlk; jb++) {
        __syncthreads();   // previous P/V reads complete (and Q visible on jb=0)

        // Load K tile (transposed) and V tile (natural)
        const float* kr; const float* vr;
        if (jb < nPrefix) {
            size_t base = ((size_t)(b*Hh + h)*Pp + jb*64 + lr) * Dd;
            kr = cache_k + base;
            vr = cache_v + base;
        } else {
            size_t base = ((size_t)(b*Tt + (jb - nPrefix)*64 + lr))*C3 + h*Dd;
            kr = qkv + base + Cc;
            vr = qkv + base + 2*Cc;
        }
        #pragma unroll
        for (int u = 0; u < 4; u++) {
            int d4 = (lq + 4*u) * 4;
            float4 kv = *(const float4*)&kr[d4];
            sKP[(d4+0)*FP + lr] = kv.x;
            sKP[(d4+1)*FP + lr] = kv.y;
            sKP[(d4+2)*FP + lr] = kv.z;
            sKP[(d4+3)*FP + lr] = kv.w;
            *(float4*)&sV[lr*FP + d4] = *(const float4*)&vr[d4];
        }
        __syncthreads();

        // S = Q K^T  (Q pre-scaled)
        float S[4][4];
        #pragma unroll
        for (int i = 0; i < 4; i++)
            #pragma unroll
            for (int j = 0; j < 4; j++) S[i][j] = 0.f;

        #pragma unroll 8
        for (int d = 0; d < 64; d++) {
            float4 qv = *(const float4*)&sQt[d*FP + ty4];
            float4 kv = *(const float4*)&sKP[d*FP + tx4];
            float qa[4] = {qv.x, qv.y, qv.z, qv.w};
            float ka[4] = {kv.x, kv.y, kv.z, kv.w};
            #pragma unroll
            for (int i = 0; i < 4; i++)
                #pragma unroll
                for (int j = 0; j < 4; j++)
                    S[i][j] = fmaf(qa[i], ka[j], S[i][j]);
        }

        // Causal mask on the diagonal self tile only
        if (jb == nBlk - 1) {
            #pragma unroll
            for (int i = 0; i < 4; i++)
                #pragma unroll
                for (int j = 0; j < 4; j++)
                    if (tx4 + j > ty4 + i) S[i][j] = -1e30f;
        }

        // Online softmax (row reductions across the 16 tx lanes via shfl)
        float alpha[4];
        #pragma unroll
        for (int i = 0; i < 4; i++) {
            float rm = fmaxf(fmaxf(S[i][0], S[i][1]), fmaxf(S[i][2], S[i][3]));
            #pragma unroll
            for (int msk = 1; msk < 16; msk <<= 1)
                rm = fmaxf(rm, __shfl_xor_sync(0xffffffffu, rm, msk));
            float mn = fmaxf(m_i[i], rm);
            alpha[i] = __expf(m_i[i] - mn);
            float rs = 0.f;
            #pragma unroll
            for (int j = 0; j < 4; j++) {
                float p = __expf(S[i][j] - mn);
                S[i][j] = p;
                rs += p;
            }
            #pragma unroll
            for (int msk = 1; msk < 16; msk <<= 1)
                rs += __shfl_xor_sync(0xffffffffu, rs, msk);
            l_i[i] = l_i[i] * alpha[i] + rs;
            m_i[i] = mn;
            #pragma unroll
            for (int j = 0; j < 4; j++) O[i][j] *= alpha[i];
        }

        __syncthreads();   // all threads done reading sKP as K^T

        // Store P naturally: sKP[r][c]  (STS.128, conflict-free)
        #pragma unroll
        for (int i = 0; i < 4; i++)
            *(float4*)&sKP[(ty4+i)*FP + tx4] =
                make_float4(S[i][0], S[i][1], S[i][2], S[i][3]);
        __syncthreads();

        // O += P @ V
        #pragma unroll 8
        for (int kk = 0; kk < 64; kk++) {
            float4 vv = *(const float4*)&sV[kk*FP + tx4];
            float va[4] = {vv.x, vv.y, vv.z, vv.w};
            float pa[4];
            #pragma unroll
            for (int i = 0; i < 4; i++) pa[i] = sKP[(ty4+i)*FP + kk];
            #pragma unroll
            for (int i = 0; i < 4; i++)
                #pragma unroll
                for (int j = 0; j < 4; j++)
                    O[i][j] = fmaf(pa[i], va[j], O[i][j]);
        }
    }

    // Normalize and write y in [B, T, H*D] layout (ready for proj GEMM)
    #pragma unroll
    for (int i = 0; i < 4; i++) {
        float inv = 1.f / l_i[i];
        float4 o = make_float4(O[i][0]*inv, O[i][1]*inv, O[i][2]*inv, O[i][3]*inv);
        *(float4*)&y[((size_t)(b*Tt + q0 + ty4 + i))*Cc + h*Dd + tx4] = o;
    }
}

// ---------------------------------------------------------------------------
// Launch
// ---------------------------------------------------------------------------
extern "C" void kernel_launch(void* const* d_in, const int* in_sizes, int n_in,
                              void* d_out, int out_size)
{
    const float* x       = (const float*)d_in[0];
    const float* W_attn  = (const float*)d_in[1];
    const float* W_proj  = (const float*)d_in[2];
    const float* cache_k = (const float*)d_in[3];
    const float* cache_v = (const float*)d_in[4];
    float* out = (float*)d_out;

    float *qkv_p = nullptr, *y_p = nullptr;
    cudaGetSymbolAddress((void**)&qkv_p, g_qkv);
    cudaGetSymbolAddress((void**)&y_p, g_y);

    const int smem_flash = 3 * 64 * FP * (int)sizeof(float);   // 52224 B
    cudaFuncSetAttribute(flash_kernel,
                         cudaFuncAttributeMaxDynamicSharedMemorySize, smem_flash);

    dim3 blk(256);
    // 1) qkv = x @ W_attn : [4096, 3072]
    sgemm_kernel<<<dim3(C3/128, (Bb*Tt)/128), blk>>>(x, W_attn, qkv_p,
                                                     Bb*Tt, C3, Cc);
    // 2) flash attention over prefix + causal self
    flash_kernel<<<dim3(Tt/64, Hh, Bb), blk, smem_flash>>>(qkv_p, cache_k,
                                                           cache_v, y_p);
    // 3) out = y @ W_proj : [4096, 1024]
    sgemm_kernel<<<dim3(Cc/128, (Bb*Tt)/128), blk>>>(y_p, W_proj, out,
                                                     Bb*Tt, Cc, Cc);
}